// round 3
// baseline (speedup 1.0000x reference)
#include <cuda_runtime.h>
#include <math.h>

// Problem constants
constexpr int B  = 2;
constexpr int S  = 2048;
constexpr int DM = 1024;   // d_model
constexpr int H  = 16;
constexpr int DK = 64;
constexpr int MR = B * S;  // 4096 rows

// Scratch (allocation-free: __device__ globals)
__device__ float g_Q[MR * DM];
__device__ float g_K[MR * DM];
__device__ float g_V[MR * DM];
__device__ float g_A[MR * DM];

// ---------------------------------------------------------------------------
// SGEMM: C[M,N] = A[M,K] @ W[K,N] + bias[N]   (M=4096, N=K=1024, all mult of tiles)
// 128x128 block tile, BK=8, 256 threads, 8x8 per-thread register tile.
// ---------------------------------------------------------------------------
#define BM 128
#define BN 128
#define BKD 8
#define TM 8
#define TN 8

__global__ __launch_bounds__(256) void sgemm_bias(
    const float* __restrict__ A, const float* __restrict__ W,
    const float* __restrict__ bias, float* __restrict__ C,
    int M, int N, int K)
{
    __shared__ float As[BKD][BM];   // A tile transposed: As[k][m]
    __shared__ float Bs[BKD][BN];   // W tile natural:    Bs[k][n]

    const int tid   = threadIdx.x;
    const int mBase = blockIdx.y * BM;
    const int nBase = blockIdx.x * BN;

    const int aRow = tid >> 1;          // 0..127
    const int aCol = (tid & 1) * 4;     // 0 or 4
    const int bRow = tid >> 5;          // 0..7
    const int bCol = (tid & 31) * 4;    // 0..124
    const int tRow = (tid >> 4) * TM;   // 0..120
    const int tCol = (tid & 15) * TN;   // 0..120

    const float* Ag = A + (size_t)(mBase + aRow) * K + aCol;
    const float* Wg = W + (size_t)bRow * N + nBase + bCol;

    float acc[TM][TN];
#pragma unroll
    for (int i = 0; i < TM; i++)
#pragma unroll
        for (int j = 0; j < TN; j++) acc[i][j] = 0.0f;

    for (int k0 = 0; k0 < K; k0 += BKD) {
        float4 av = *(const float4*)(Ag + k0);
        As[aCol + 0][aRow] = av.x;
        As[aCol + 1][aRow] = av.y;
        As[aCol + 2][aRow] = av.z;
        As[aCol + 3][aRow] = av.w;
        *(float4*)&Bs[bRow][bCol] = *(const float4*)(Wg + (size_t)k0 * N);
        __syncthreads();

#pragma unroll
        for (int k = 0; k < BKD; k++) {
            float ra[TM], rb[TN];
            *(float4*)&ra[0] = *(const float4*)&As[k][tRow];
            *(float4*)&ra[4] = *(const float4*)&As[k][tRow + 4];
            *(float4*)&rb[0] = *(const float4*)&Bs[k][tCol];
            *(float4*)&rb[4] = *(const float4*)&Bs[k][tCol + 4];
#pragma unroll
            for (int i = 0; i < TM; i++)
#pragma unroll
                for (int j = 0; j < TN; j++)
                    acc[i][j] = fmaf(ra[i], rb[j], acc[i][j]);
        }
        __syncthreads();
    }

#pragma unroll
    for (int i = 0; i < TM; i++) {
        float* Crow = C + (size_t)(mBase + tRow + i) * N + nBase + tCol;
#pragma unroll
        for (int j = 0; j < TN; j += 4) {
            float4 o;
            o.x = acc[i][j + 0] + bias[nBase + tCol + j + 0];
            o.y = acc[i][j + 1] + bias[nBase + tCol + j + 1];
            o.z = acc[i][j + 2] + bias[nBase + tCol + j + 2];
            o.w = acc[i][j + 3] + bias[nBase + tCol + j + 3];
            *(float4*)(Crow + j) = o;
        }
    }
}

// ---------------------------------------------------------------------------
// Flash attention: per (batch, head, 64-row q-tile) CTA, 64-wide kv tiles.
// Q/K/V are [B*S, H*DK] row-major (head h at col offset h*DK).
// smem (dynamic 64KB): Qs[64][64] (pre-scaled), Kt[64][64] (K transposed: [k][c]),
//                      Vs[64][64] ([j][d]), Ps[64][64] ([r][j]).
// Thread (tr,tc) in 16x16 grid owns rows r0..r0+3 and cols c0..c0+3.
// ---------------------------------------------------------------------------
#define AQ 64
#define AKV 64

__global__ __launch_bounds__(256) void attn_kernel(
    const float* __restrict__ Q, const float* __restrict__ K,
    const float* __restrict__ V, float* __restrict__ O)
{
    extern __shared__ float sm[];
    float* Qs = sm;                // 64*64
    float* Kt = sm + 64 * 64;      // [k][c]
    float* Vs = sm + 2 * 64 * 64;  // [j][d]
    float* Ps = sm + 3 * 64 * 64;  // [r][j]

    const int tid = threadIdx.x;
    const int b  = blockIdx.z, h = blockIdx.y;
    const int q0 = blockIdx.x * AQ;

    const float* Qg = Q + ((size_t)(b * S + q0)) * DM + h * DK;
    const float* Kg = K + ((size_t)(b * S)) * DM + h * DK;
    const float* Vg = V + ((size_t)(b * S)) * DM + h * DK;
    float*       Og = O + ((size_t)(b * S + q0)) * DM + h * DK;

    const int lrow = tid >> 2;         // 0..63 (tile row for loads)
    const int lcb  = (tid & 3) * 16;   // col base for loads
    const int r0 = (tid >> 4) * 4;     // this thread's 4 q-rows
    const int c0 = (tid & 15) * 4;     // this thread's 4 kv-cols / d-cols

    // Load Q tile, pre-scaled by 1/sqrt(DK)
    {
        const float* src = Qg + (size_t)lrow * DM + lcb;
#pragma unroll
        for (int u = 0; u < 4; u++) {
            float4 v = *(const float4*)(src + u * 4);
            v.x *= 0.125f; v.y *= 0.125f; v.z *= 0.125f; v.w *= 0.125f;
            *(float4*)&Qs[lrow * 64 + lcb + u * 4] = v;
        }
    }

    float m[4], l[4], o[4][4];
#pragma unroll
    for (int i = 0; i < 4; i++) {
        m[i] = -1e30f; l[i] = 0.0f;
#pragma unroll
        for (int j = 0; j < 4; j++) o[i][j] = 0.0f;
    }

    for (int kv0 = 0; kv0 < S; kv0 += AKV) {
        __syncthreads();  // prev-iter consumers done (covers Q-load for iter 0)

        // Load K tile transposed, V tile natural
        {
            const float* ks = Kg + (size_t)(kv0 + lrow) * DM + lcb;
#pragma unroll
            for (int u = 0; u < 4; u++) {
                float4 v = *(const float4*)(ks + u * 4);
                int kk = lcb + u * 4;
                Kt[(kk + 0) * 64 + lrow] = v.x;
                Kt[(kk + 1) * 64 + lrow] = v.y;
                Kt[(kk + 2) * 64 + lrow] = v.z;
                Kt[(kk + 3) * 64 + lrow] = v.w;
            }
            const float* vsrc = Vg + (size_t)(kv0 + lrow) * DM + lcb;
#pragma unroll
            for (int u = 0; u < 4; u++)
                *(float4*)&Vs[lrow * 64 + lcb + u * 4] = *(const float4*)(vsrc + u * 4);
        }
        __syncthreads();

        // S tile = (Q*scale) @ K^T : s[i][j], rows r0+i, cols c0+j
        float s[4][4];
#pragma unroll
        for (int i = 0; i < 4; i++)
#pragma unroll
            for (int j = 0; j < 4; j++) s[i][j] = 0.0f;

#pragma unroll 8
        for (int k = 0; k < DK; k++) {
            float4 kv = *(const float4*)&Kt[k * 64 + c0];   // contiguous across lanes
            float q0v = Qs[(r0 + 0) * 64 + k];              // broadcast
            float q1v = Qs[(r0 + 1) * 64 + k];
            float q2v = Qs[(r0 + 2) * 64 + k];
            float q3v = Qs[(r0 + 3) * 64 + k];
            s[0][0] = fmaf(q0v, kv.x, s[0][0]); s[0][1] = fmaf(q0v, kv.y, s[0][1]);
            s[0][2] = fmaf(q0v, kv.z, s[0][2]); s[0][3] = fmaf(q0v, kv.w, s[0][3]);
            s[1][0] = fmaf(q1v, kv.x, s[1][0]); s[1][1] = fmaf(q1v, kv.y, s[1][1]);
            s[1][2] = fmaf(q1v, kv.z, s[1][2]); s[1][3] = fmaf(q1v, kv.w, s[1][3]);
            s[2][0] = fmaf(q2v, kv.x, s[2][0]); s[2][1] = fmaf(q2v, kv.y, s[2][1]);
            s[2][2] = fmaf(q2v, kv.z, s[2][2]); s[2][3] = fmaf(q2v, kv.w, s[2][3]);
            s[3][0] = fmaf(q3v, kv.x, s[3][0]); s[3][1] = fmaf(q3v, kv.y, s[3][1]);
            s[3][2] = fmaf(q3v, kv.z, s[3][2]); s[3][3] = fmaf(q3v, kv.w, s[3][3]);
        }

        // Online softmax per row (reduce across the 16 threads of a row-group;
        // those are lanes [tr*16, tr*16+16) -> width-16 shfl butterflies)
#pragma unroll
        for (int i = 0; i < 4; i++) {
            float mx = fmaxf(fmaxf(s[i][0], s[i][1]), fmaxf(s[i][2], s[i][3]));
#pragma unroll
            for (int off = 1; off < 16; off <<= 1)
                mx = fmaxf(mx, __shfl_xor_sync(0xffffffffu, mx, off, 16));
            float mn    = fmaxf(m[i], mx);
            float alpha = __expf(m[i] - mn);
            m[i] = mn;
            float p0 = __expf(s[i][0] - mn);
            float p1 = __expf(s[i][1] - mn);
            float p2 = __expf(s[i][2] - mn);
            float p3 = __expf(s[i][3] - mn);
            float ls = (p0 + p1) + (p2 + p3);
#pragma unroll
            for (int off = 1; off < 16; off <<= 1)
                ls += __shfl_xor_sync(0xffffffffu, ls, off, 16);
            l[i] = l[i] * alpha + ls;
            o[i][0] *= alpha; o[i][1] *= alpha; o[i][2] *= alpha; o[i][3] *= alpha;
            float4 pv; pv.x = p0; pv.y = p1; pv.z = p2; pv.w = p3;
            *(float4*)&Ps[(r0 + i) * 64 + c0] = pv;
        }
        __syncthreads();

        // O += P @ V
#pragma unroll 8
        for (int j = 0; j < AKV; j++) {
            float4 vv = *(const float4*)&Vs[j * 64 + c0];   // contiguous across lanes
            float p0v = Ps[(r0 + 0) * 64 + j];              // broadcast
            float p1v = Ps[(r0 + 1) * 64 + j];
            float p2v = Ps[(r0 + 2) * 64 + j];
            float p3v = Ps[(r0 + 3) * 64 + j];
            o[0][0] = fmaf(p0v, vv.x, o[0][0]); o[0][1] = fmaf(p0v, vv.y, o[0][1]);
            o[0][2] = fmaf(p0v, vv.z, o[0][2]); o[0][3] = fmaf(p0v, vv.w, o[0][3]);
            o[1][0] = fmaf(p1v, vv.x, o[1][0]); o[1][1] = fmaf(p1v, vv.y, o[1][1]);
            o[1][2] = fmaf(p1v, vv.z, o[1][2]); o[1][3] = fmaf(p1v, vv.w, o[1][3]);
            o[2][0] = fmaf(p2v, vv.x, o[2][0]); o[2][1] = fmaf(p2v, vv.y, o[2][1]);
            o[2][2] = fmaf(p2v, vv.z, o[2][2]); o[2][3] = fmaf(p2v, vv.w, o[2][3]);
            o[3][0] = fmaf(p3v, vv.x, o[3][0]); o[3][1] = fmaf(p3v, vv.y, o[3][1]);
            o[3][2] = fmaf(p3v, vv.z, o[3][2]); o[3][3] = fmaf(p3v, vv.w, o[3][3]);
        }
    }

    // Normalize and store
#pragma unroll
    for (int i = 0; i < 4; i++) {
        float inv = 1.0f / l[i];
        float4 ov;
        ov.x = o[i][0] * inv; ov.y = o[i][1] * inv;
        ov.z = o[i][2] * inv; ov.w = o[i][3] * inv;
        *(float4*)(Og + (size_t)(r0 + i) * DM + c0) = ov;
    }
}

// ---------------------------------------------------------------------------
// Launch
// ---------------------------------------------------------------------------
extern "C" void kernel_launch(void* const* d_in, const int* in_sizes, int n_in,
                              void* d_out, int out_size)
{
    const float* x  = (const float*)d_in[0];
    const float* wq = (const float*)d_in[1];
    const float* bq = (const float*)d_in[2];
    const float* wk = (const float*)d_in[3];
    const float* bk = (const float*)d_in[4];
    const float* wv = (const float*)d_in[5];
    const float* bv = (const float*)d_in[6];
    const float* wo = (const float*)d_in[7];
    const float* bo = (const float*)d_in[8];
    float* out = (float*)d_out;

    float *Qp, *Kp, *Vp, *Ap;
    cudaGetSymbolAddress((void**)&Qp, g_Q);
    cudaGetSymbolAddress((void**)&Kp, g_K);
    cudaGetSymbolAddress((void**)&Vp, g_V);
    cudaGetSymbolAddress((void**)&Ap, g_A);

    const int smemAttn = 4 * 64 * 64 * (int)sizeof(float);  // 64KB
    cudaFuncSetAttribute(attn_kernel, cudaFuncAttributeMaxDynamicSharedMemorySize, smemAttn);

    dim3 gGemm(DM / BN, MR / BM);   // (8, 32)
    sgemm_bias<<<gGemm, 256>>>(x, wq, bq, Qp, MR, DM, DM);
    sgemm_bias<<<gGemm, 256>>>(x, wk, bk, Kp, MR, DM, DM);
    sgemm_bias<<<gGemm, 256>>>(x, wv, bv, Vp, MR, DM, DM);

    dim3 gAttn(S / AQ, H, B);       // (32, 16, 2)
    attn_kernel<<<gAttn, 256, smemAttn>>>(Qp, Kp, Vp, Ap);

    sgemm_bias<<<gGemm, 256>>>(Ap, wo, bo, out, MR, DM, DM);
}

// round 5
// speedup vs baseline: 1.3416x; 1.3416x over previous
#include <cuda_runtime.h>
#include <cuda_bf16.h>
#include <cstdint>
#include <math.h>

// Problem constants
constexpr int B  = 2;
constexpr int S  = 2048;
constexpr int DM = 1024;   // d_model
constexpr int H  = 16;
constexpr int DK = 64;
constexpr int MR = B * S;  // 4096 rows

// ---------------------------------------------------------------------------
// Scratch (allocation-free: __device__ globals)
// ---------------------------------------------------------------------------
__device__ float g_Q[MR * DM];
__device__ float g_K[MR * DM];
__device__ float g_V[MR * DM];
__device__ float g_A[MR * DM];
__device__ __nv_bfloat16 g_xh[MR * DM];
__device__ __nv_bfloat16 g_xl[MR * DM];
__device__ __nv_bfloat16 g_ah[MR * DM];
__device__ __nv_bfloat16 g_al[MR * DM];
__device__ __nv_bfloat16 g_wth[4 * DM * DM];  // transposed weights, hi part
__device__ __nv_bfloat16 g_wtl[4 * DM * DM];  // transposed weights, lo part

// ---------------------------------------------------------------------------
// mma.sync / ldmatrix helpers (non-'a' PTX surface: works on compute_103)
// ---------------------------------------------------------------------------
__device__ __forceinline__ uint32_t smem_u32(const void* p) {
    uint32_t a;
    asm("{ .reg .u64 t; cvta.to.shared.u64 t, %1; cvt.u32.u64 %0, t; }"
        : "=r"(a) : "l"(p));
    return a;
}

__device__ __forceinline__ void ldmx4(uint32_t* r, uint32_t addr) {
    asm volatile("ldmatrix.sync.aligned.m8n8.x4.shared.b16 {%0,%1,%2,%3}, [%4];"
                 : "=r"(r[0]), "=r"(r[1]), "=r"(r[2]), "=r"(r[3]) : "r"(addr));
}
__device__ __forceinline__ void ldmx2(uint32_t* r, uint32_t addr) {
    asm volatile("ldmatrix.sync.aligned.m8n8.x2.shared.b16 {%0,%1}, [%2];"
                 : "=r"(r[0]), "=r"(r[1]) : "r"(addr));
}
__device__ __forceinline__ void mma16816(float* c, const uint32_t* a, const uint32_t* b) {
    asm volatile(
        "mma.sync.aligned.m16n8k16.row.col.f32.bf16.bf16.f32 "
        "{%0,%1,%2,%3}, {%4,%5,%6,%7}, {%8,%9}, {%0,%1,%2,%3};"
        : "+f"(c[0]), "+f"(c[1]), "+f"(c[2]), "+f"(c[3])
        : "r"(a[0]), "r"(a[1]), "r"(a[2]), "r"(a[3]), "r"(b[0]), "r"(b[1]));
}

// ---------------------------------------------------------------------------
// Split / transpose helpers
// ---------------------------------------------------------------------------
__global__ __launch_bounds__(256) void split2_kernel(
    const float* __restrict__ x, __nv_bfloat16* __restrict__ h,
    __nv_bfloat16* __restrict__ l, int n4)
{
    int i = blockIdx.x * blockDim.x + threadIdx.x;
    if (i >= n4) return;
    float4 v = ((const float4*)x)[i];
    __nv_bfloat16 ha[4], la[4];
    float f[4] = {v.x, v.y, v.z, v.w};
#pragma unroll
    for (int j = 0; j < 4; j++) {
        ha[j] = __float2bfloat16(f[j]);
        la[j] = __float2bfloat16(f[j] - __bfloat162float(ha[j]));
    }
    ((uint2*)h)[i] = *(const uint2*)ha;
    ((uint2*)l)[i] = *(const uint2*)la;
}

// W [K,N] fp32 -> Wt hi/lo [N,K] bf16
__global__ __launch_bounds__(256) void tsplit_kernel(
    const float* __restrict__ W, __nv_bfloat16* __restrict__ Th,
    __nv_bfloat16* __restrict__ Tl)
{
    __shared__ float t[32][33];
    const int n0 = blockIdx.x * 32, k0 = blockIdx.y * 32;
    const int tx = threadIdx.x, ty = threadIdx.y;  // 32 x 8
    for (int i = ty; i < 32; i += 8)
        t[i][tx] = W[(size_t)(k0 + i) * DM + n0 + tx];
    __syncthreads();
    for (int i = ty; i < 32; i += 8) {
        float v = t[tx][i];  // = W[k0+tx][n0+i]
        __nv_bfloat16 hi = __float2bfloat16(v);
        __nv_bfloat16 lo = __float2bfloat16(v - __bfloat162float(hi));
        Th[(size_t)(n0 + i) * DM + k0 + tx] = hi;
        Tl[(size_t)(n0 + i) * DM + k0 + tx] = lo;
    }
}

// ---------------------------------------------------------------------------
// mma.sync GEMM: C[M,N] = A[M,K] @ Wt^T + bias via bf16x3 split.
// A hi/lo: [M,K] bf16 K-major. Wt hi/lo: [N,K] bf16 K-major.
// CTA 128x128 tile, 256 threads (8 warps, 2x4), warp tile 64x32.
// BK=64 chunk; smem tiles padded to stride 72 bf16 (conflict-free ldmatrix).
// blockIdx.z selects (weight slab, bias, output) so QKV fuses into one grid.
// ---------------------------------------------------------------------------
constexpr int GK = 64;                 // k-chunk
constexpr int GPAD = 72;               // padded row stride (bf16 elems)
constexpr int GT_BYTES = 128 * GPAD * 2;          // 18432 per tile
constexpr int SMG_TOTAL = 4 * GT_BYTES;           // 73728

__global__ __launch_bounds__(256) void gemm_mma(
    const __nv_bfloat16* __restrict__ Ah, const __nv_bfloat16* __restrict__ Al,
    const __nv_bfloat16* __restrict__ Wh0, const __nv_bfloat16* __restrict__ Wl0,
    const float* __restrict__ b0, const float* __restrict__ b1,
    const float* __restrict__ b2,
    float* __restrict__ O0, float* __restrict__ O1, float* __restrict__ O2)
{
    extern __shared__ char smem[];
    const int z = blockIdx.z;
    const __nv_bfloat16* Wh = Wh0 + (size_t)z * DM * DM;
    const __nv_bfloat16* Wl = Wl0 + (size_t)z * DM * DM;
    const float* bias = (z == 0) ? b0 : ((z == 1) ? b1 : b2);
    float*       Cout = (z == 0) ? O0 : ((z == 1) ? O1 : O2);

    const int tid  = threadIdx.x;
    const int wid  = tid >> 5, lane = tid & 31;
    const int mBase = blockIdx.y * 128, nBase = blockIdx.x * 128;

    const uint32_t sb = smem_u32(smem);
    const uint32_t sAH = sb;
    const uint32_t sAL = sb + GT_BYTES;
    const uint32_t sBH = sb + 2 * GT_BYTES;
    const uint32_t sBL = sb + 3 * GT_BYTES;

    // warp layout: 2 (m) x 4 (n)
    const int wm = wid >> 2, wn = wid & 3;
    const int mrow0 = wm * 64, nrow0 = wn * 32;

    // ldmatrix per-lane byte offsets (row stride 144 B)
    const uint32_t aOff = (uint32_t)(((lane & 7) + ((lane >> 3) & 1) * 8) * 144
                                     + (lane >> 4) * 16);
    const int l15 = lane & 15;
    const uint32_t bOff = (uint32_t)((l15 & 7) * 144 + (l15 >> 3) * 16);

    // global fill addressing: 32 rows/pass, 8 uint4 chunks per row
    const int frow = tid >> 3;           // 0..31
    const int fcol = (tid & 7) * 8;      // bf16 elems

    const __nv_bfloat16* gAh = Ah + (size_t)mBase * DM;
    const __nv_bfloat16* gAl = Al + (size_t)mBase * DM;
    const __nv_bfloat16* gBh = Wh + (size_t)nBase * DM;
    const __nv_bfloat16* gBl = Wl + (size_t)nBase * DM;

    float c[4][4][4];
#pragma unroll
    for (int i = 0; i < 4; i++)
#pragma unroll
        for (int j = 0; j < 4; j++)
#pragma unroll
            for (int e = 0; e < 4; e++) c[i][j][e] = 0.0f;

    for (int k0 = 0; k0 < DM; k0 += GK) {
        __syncthreads();  // protect previous chunk's reads
#pragma unroll
        for (int p = 0; p < 4; p++) {
            const int row = p * 32 + frow;
            const size_t go = (size_t)row * DM + k0 + fcol;
            const uint32_t so = (uint32_t)(row * GPAD + fcol) * 2;
            *(uint4*)(smem + (sAH - sb) + so) = *(const uint4*)(gAh + go);
            *(uint4*)(smem + (sAL - sb) + so) = *(const uint4*)(gAl + go);
            *(uint4*)(smem + (sBH - sb) + so) = *(const uint4*)(gBh + go);
            *(uint4*)(smem + (sBL - sb) + so) = *(const uint4*)(gBl + go);
        }
        __syncthreads();

#pragma unroll
        for (int ks = 0; ks < GK / 16; ks++) {
            const uint32_t kb = (uint32_t)(ks * 32);  // 16 bf16 = 32 B
            uint32_t ah[4][4], al[4][4], bh[4][2], bl[4][2];
#pragma unroll
            for (int mf = 0; mf < 4; mf++) {
                const uint32_t ro = (uint32_t)((mrow0 + mf * 16) * 144) + kb + aOff;
                ldmx4(ah[mf], sAH + ro);
                ldmx4(al[mf], sAL + ro);
            }
#pragma unroll
            for (int nf = 0; nf < 4; nf++) {
                const uint32_t ro = (uint32_t)((nrow0 + nf * 8) * 144) + kb + bOff;
                ldmx2(bh[nf], sBH + ro);
                ldmx2(bl[nf], sBL + ro);
            }
#pragma unroll
            for (int mf = 0; mf < 4; mf++)
#pragma unroll
                for (int nf = 0; nf < 4; nf++) {
                    mma16816(c[mf][nf], ah[mf], bh[nf]);
                    mma16816(c[mf][nf], al[mf], bh[nf]);
                    mma16816(c[mf][nf], ah[mf], bl[nf]);
                }
        }
    }

    // Epilogue: C frag layout m16n8.f32 — lane l: rows l/4 and l/4+8, cols (l%4)*2,+1
    const int crow = lane >> 2, ccol = (lane & 3) * 2;
#pragma unroll
    for (int mf = 0; mf < 4; mf++) {
#pragma unroll
        for (int nf = 0; nf < 4; nf++) {
            const int r  = mBase + mrow0 + mf * 16 + crow;
            const int cc = nBase + nrow0 + nf * 8 + ccol;
            const float bx = bias[cc], by = bias[cc + 1];
            float2 v0 = { c[mf][nf][0] + bx, c[mf][nf][1] + by };
            float2 v1 = { c[mf][nf][2] + bx, c[mf][nf][3] + by };
            *(float2*)(Cout + (size_t)r * DM + cc)       = v0;
            *(float2*)(Cout + (size_t)(r + 8) * DM + cc) = v1;
        }
    }
}

// ===========================================================================
// Flash attention (unchanged from passing baseline)
// ===========================================================================
#define AQ 64
#define AKV 64

__global__ __launch_bounds__(256) void attn_kernel(
    const float* __restrict__ Q, const float* __restrict__ K,
    const float* __restrict__ V, float* __restrict__ O)
{
    extern __shared__ float sm[];
    float* Qs = sm;
    float* Kt = sm + 64 * 64;
    float* Vs = sm + 2 * 64 * 64;
    float* Ps = sm + 3 * 64 * 64;

    const int tid = threadIdx.x;
    const int b  = blockIdx.z, h = blockIdx.y;
    const int q0 = blockIdx.x * AQ;

    const float* Qg = Q + ((size_t)(b * S + q0)) * DM + h * DK;
    const float* Kg = K + ((size_t)(b * S)) * DM + h * DK;
    const float* Vg = V + ((size_t)(b * S)) * DM + h * DK;
    float*       Og = O + ((size_t)(b * S + q0)) * DM + h * DK;

    const int lrow = tid >> 2;
    const int lcb  = (tid & 3) * 16;
    const int r0 = (tid >> 4) * 4;
    const int c0 = (tid & 15) * 4;

    {
        const float* src = Qg + (size_t)lrow * DM + lcb;
#pragma unroll
        for (int u = 0; u < 4; u++) {
            float4 v = *(const float4*)(src + u * 4);
            v.x *= 0.125f; v.y *= 0.125f; v.z *= 0.125f; v.w *= 0.125f;
            *(float4*)&Qs[lrow * 64 + lcb + u * 4] = v;
        }
    }

    float m[4], l[4], o[4][4];
#pragma unroll
    for (int i = 0; i < 4; i++) {
        m[i] = -1e30f; l[i] = 0.0f;
#pragma unroll
        for (int j = 0; j < 4; j++) o[i][j] = 0.0f;
    }

    for (int kv0 = 0; kv0 < S; kv0 += AKV) {
        __syncthreads();
        {
            const float* ks = Kg + (size_t)(kv0 + lrow) * DM + lcb;
#pragma unroll
            for (int u = 0; u < 4; u++) {
                float4 v = *(const float4*)(ks + u * 4);
                int kk = lcb + u * 4;
                Kt[(kk + 0) * 64 + lrow] = v.x;
                Kt[(kk + 1) * 64 + lrow] = v.y;
                Kt[(kk + 2) * 64 + lrow] = v.z;
                Kt[(kk + 3) * 64 + lrow] = v.w;
            }
            const float* vsrc = Vg + (size_t)(kv0 + lrow) * DM + lcb;
#pragma unroll
            for (int u = 0; u < 4; u++)
                *(float4*)&Vs[lrow * 64 + lcb + u * 4] = *(const float4*)(vsrc + u * 4);
        }
        __syncthreads();

        float s[4][4];
#pragma unroll
        for (int i = 0; i < 4; i++)
#pragma unroll
            for (int j = 0; j < 4; j++) s[i][j] = 0.0f;

#pragma unroll 8
        for (int k = 0; k < DK; k++) {
            float4 kv = *(const float4*)&Kt[k * 64 + c0];
            float q0v = Qs[(r0 + 0) * 64 + k];
            float q1v = Qs[(r0 + 1) * 64 + k];
            float q2v = Qs[(r0 + 2) * 64 + k];
            float q3v = Qs[(r0 + 3) * 64 + k];
            s[0][0] = fmaf(q0v, kv.x, s[0][0]); s[0][1] = fmaf(q0v, kv.y, s[0][1]);
            s[0][2] = fmaf(q0v, kv.z, s[0][2]); s[0][3] = fmaf(q0v, kv.w, s[0][3]);
            s[1][0] = fmaf(q1v, kv.x, s[1][0]); s[1][1] = fmaf(q1v, kv.y, s[1][1]);
            s[1][2] = fmaf(q1v, kv.z, s[1][2]); s[1][3] = fmaf(q1v, kv.w, s[1][3]);
            s[2][0] = fmaf(q2v, kv.x, s[2][0]); s[2][1] = fmaf(q2v, kv.y, s[2][1]);
            s[2][2] = fmaf(q2v, kv.z, s[2][2]); s[2][3] = fmaf(q2v, kv.w, s[2][3]);
            s[3][0] = fmaf(q3v, kv.x, s[3][0]); s[3][1] = fmaf(q3v, kv.y, s[3][1]);
            s[3][2] = fmaf(q3v, kv.z, s[3][2]); s[3][3] = fmaf(q3v, kv.w, s[3][3]);
        }

#pragma unroll
        for (int i = 0; i < 4; i++) {
            float mx = fmaxf(fmaxf(s[i][0], s[i][1]), fmaxf(s[i][2], s[i][3]));
#pragma unroll
            for (int off = 1; off < 16; off <<= 1)
                mx = fmaxf(mx, __shfl_xor_sync(0xffffffffu, mx, off, 16));
            float mn    = fmaxf(m[i], mx);
            float alpha = __expf(m[i] - mn);
            m[i] = mn;
            float p0 = __expf(s[i][0] - mn);
            float p1 = __expf(s[i][1] - mn);
            float p2 = __expf(s[i][2] - mn);
            float p3 = __expf(s[i][3] - mn);
            float ls = (p0 + p1) + (p2 + p3);
#pragma unroll
            for (int off = 1; off < 16; off <<= 1)
                ls += __shfl_xor_sync(0xffffffffu, ls, off, 16);
            l[i] = l[i] * alpha + ls;
            o[i][0] *= alpha; o[i][1] *= alpha; o[i][2] *= alpha; o[i][3] *= alpha;
            float4 pv; pv.x = p0; pv.y = p1; pv.z = p2; pv.w = p3;
            *(float4*)&Ps[(r0 + i) * 64 + c0] = pv;
        }
        __syncthreads();

#pragma unroll 8
        for (int j = 0; j < AKV; j++) {
            float4 vv = *(const float4*)&Vs[j * 64 + c0];
            float p0v = Ps[(r0 + 0) * 64 + j];
            float p1v = Ps[(r0 + 1) * 64 + j];
            float p2v = Ps[(r0 + 2) * 64 + j];
            float p3v = Ps[(r0 + 3) * 64 + j];
            o[0][0] = fmaf(p0v, vv.x, o[0][0]); o[0][1] = fmaf(p0v, vv.y, o[0][1]);
            o[0][2] = fmaf(p0v, vv.z, o[0][2]); o[0][3] = fmaf(p0v, vv.w, o[0][3]);
            o[1][0] = fmaf(p1v, vv.x, o[1][0]); o[1][1] = fmaf(p1v, vv.y, o[1][1]);
            o[1][2] = fmaf(p1v, vv.z, o[1][2]); o[1][3] = fmaf(p1v, vv.w, o[1][3]);
            o[2][0] = fmaf(p2v, vv.x, o[2][0]); o[2][1] = fmaf(p2v, vv.y, o[2][1]);
            o[2][2] = fmaf(p2v, vv.z, o[2][2]); o[2][3] = fmaf(p2v, vv.w, o[2][3]);
            o[3][0] = fmaf(p3v, vv.x, o[3][0]); o[3][1] = fmaf(p3v, vv.y, o[3][1]);
            o[3][2] = fmaf(p3v, vv.z, o[3][2]); o[3][3] = fmaf(p3v, vv.w, o[3][3]);
        }
    }

#pragma unroll
    for (int i = 0; i < 4; i++) {
        float inv = 1.0f / l[i];
        float4 ov;
        ov.x = o[i][0] * inv; ov.y = o[i][1] * inv;
        ov.z = o[i][2] * inv; ov.w = o[i][3] * inv;
        *(float4*)(Og + (size_t)(r0 + i) * DM + c0) = ov;
    }
}

// ===========================================================================
// Launch
// ===========================================================================
extern "C" void kernel_launch(void* const* d_in, const int* in_sizes, int n_in,
                              void* d_out, int out_size)
{
    const float* x  = (const float*)d_in[0];
    const float* wq = (const float*)d_in[1];
    const float* bq = (const float*)d_in[2];
    const float* wk = (const float*)d_in[3];
    const float* bk = (const float*)d_in[4];
    const float* wv = (const float*)d_in[5];
    const float* bv = (const float*)d_in[6];
    const float* wo = (const float*)d_in[7];
    const float* bo = (const float*)d_in[8];
    float* out = (float*)d_out;

    float *Qp, *Kp, *Vp, *Ap;
    __nv_bfloat16 *xh, *xl, *ah, *al, *wth, *wtl;
    cudaGetSymbolAddress((void**)&Qp, g_Q);
    cudaGetSymbolAddress((void**)&Kp, g_K);
    cudaGetSymbolAddress((void**)&Vp, g_V);
    cudaGetSymbolAddress((void**)&Ap, g_A);
    cudaGetSymbolAddress((void**)&xh, g_xh);
    cudaGetSymbolAddress((void**)&xl, g_xl);
    cudaGetSymbolAddress((void**)&ah, g_ah);
    cudaGetSymbolAddress((void**)&al, g_al);
    cudaGetSymbolAddress((void**)&wth, g_wth);
    cudaGetSymbolAddress((void**)&wtl, g_wtl);

    cudaFuncSetAttribute(gemm_mma, cudaFuncAttributeMaxDynamicSharedMemorySize, SMG_TOTAL);
    const int smemAttn = 4 * 64 * 64 * (int)sizeof(float);  // 64KB
    cudaFuncSetAttribute(attn_kernel, cudaFuncAttributeMaxDynamicSharedMemorySize, smemAttn);

    const size_t WSZ = (size_t)DM * DM;

    // 1) operand prep
    split2_kernel<<<(MR * DM / 4 + 255) / 256, 256>>>(x, xh, xl, MR * DM / 4);
    dim3 gT(DM / 32, DM / 32);
    tsplit_kernel<<<gT, dim3(32, 8)>>>(wq, wth + 0 * WSZ, wtl + 0 * WSZ);
    tsplit_kernel<<<gT, dim3(32, 8)>>>(wk, wth + 1 * WSZ, wtl + 1 * WSZ);
    tsplit_kernel<<<gT, dim3(32, 8)>>>(wv, wth + 2 * WSZ, wtl + 2 * WSZ);
    tsplit_kernel<<<gT, dim3(32, 8)>>>(wo, wth + 3 * WSZ, wtl + 3 * WSZ);

    // 2) fused QKV projections (tensor cores via mma.sync)
    dim3 gQKV(DM / 128, MR / 128, 3);   // (8, 32, 3)
    gemm_mma<<<gQKV, 256, SMG_TOTAL>>>(xh, xl, wth, wtl, bq, bk, bv, Qp, Kp, Vp);

    // 3) attention
    dim3 gAttn(S / AQ, H, B);
    attn_kernel<<<gAttn, 256, smemAttn>>>(Qp, Kp, Vp, Ap);

    // 4) output projection
    split2_kernel<<<(MR * DM / 4 + 255) / 256, 256>>>(Ap, ah, al, MR * DM / 4);
    dim3 gO(DM / 128, MR / 128, 1);
    gemm_mma<<<gO, 256, SMG_TOTAL>>>(ah, al, wth + 3 * WSZ, wtl + 3 * WSZ,
                                     bo, bo, bo, out, out, out);
}

// round 6
// speedup vs baseline: 2.4074x; 1.7943x over previous
#include <cuda_runtime.h>
#include <cuda_bf16.h>
#include <cstdint>
#include <math.h>

// Problem constants
constexpr int B  = 2;
constexpr int S  = 2048;
constexpr int DM = 1024;   // d_model
constexpr int H  = 16;
constexpr int DK = 64;
constexpr int MR = B * S;  // 4096 rows

// ---------------------------------------------------------------------------
// Scratch (allocation-free: __device__ globals)
// ---------------------------------------------------------------------------
__device__ __nv_bfloat16 g_xh[MR * DM];
__device__ __nv_bfloat16 g_xl[MR * DM];
__device__ __nv_bfloat16 g_qh[MR * DM];
__device__ __nv_bfloat16 g_ql[MR * DM];
__device__ __nv_bfloat16 g_kh[MR * DM];
__device__ __nv_bfloat16 g_kl[MR * DM];
__device__ __nv_bfloat16 g_vh[MR * DM];
__device__ __nv_bfloat16 g_vl[MR * DM];
__device__ __nv_bfloat16 g_ah[MR * DM];
__device__ __nv_bfloat16 g_al[MR * DM];
__device__ __nv_bfloat16 g_wth[4 * DM * DM];  // transposed weights, hi part
__device__ __nv_bfloat16 g_wtl[4 * DM * DM];  // transposed weights, lo part

// ---------------------------------------------------------------------------
// mma.sync / ldmatrix helpers (non-'a' PTX surface: works on compute_103)
// ---------------------------------------------------------------------------
__device__ __forceinline__ uint32_t smem_u32(const void* p) {
    uint32_t a;
    asm("{ .reg .u64 t; cvta.to.shared.u64 t, %1; cvt.u32.u64 %0, t; }"
        : "=r"(a) : "l"(p));
    return a;
}

__device__ __forceinline__ void ldmx4(uint32_t* r, uint32_t addr) {
    asm volatile("ldmatrix.sync.aligned.m8n8.x4.shared.b16 {%0,%1,%2,%3}, [%4];"
                 : "=r"(r[0]), "=r"(r[1]), "=r"(r[2]), "=r"(r[3]) : "r"(addr));
}
__device__ __forceinline__ void ldmx2(uint32_t* r, uint32_t addr) {
    asm volatile("ldmatrix.sync.aligned.m8n8.x2.shared.b16 {%0,%1}, [%2];"
                 : "=r"(r[0]), "=r"(r[1]) : "r"(addr));
}
__device__ __forceinline__ void ldmx2t(uint32_t* r, uint32_t addr) {
    asm volatile("ldmatrix.sync.aligned.m8n8.x2.trans.shared.b16 {%0,%1}, [%2];"
                 : "=r"(r[0]), "=r"(r[1]) : "r"(addr));
}
__device__ __forceinline__ void mma16816(float* c, const uint32_t* a, const uint32_t* b) {
    asm volatile(
        "mma.sync.aligned.m16n8k16.row.col.f32.bf16.bf16.f32 "
        "{%0,%1,%2,%3}, {%4,%5,%6,%7}, {%8,%9}, {%0,%1,%2,%3};"
        : "+f"(c[0]), "+f"(c[1]), "+f"(c[2]), "+f"(c[3])
        : "r"(a[0]), "r"(a[1]), "r"(a[2]), "r"(a[3]), "r"(b[0]), "r"(b[1]));
}

__device__ __forceinline__ uint32_t pack_bf2(__nv_bfloat16 lo, __nv_bfloat16 hi) {
    __nv_bfloat162 t(lo, hi);   // .x = lo 16 bits
    return *(uint32_t*)&t;
}

// ---------------------------------------------------------------------------
// Split / transpose helpers
// ---------------------------------------------------------------------------
__global__ __launch_bounds__(256) void split2_kernel(
    const float* __restrict__ x, __nv_bfloat16* __restrict__ h,
    __nv_bfloat16* __restrict__ l, int n4)
{
    int i = blockIdx.x * blockDim.x + threadIdx.x;
    if (i >= n4) return;
    float4 v = ((const float4*)x)[i];
    __nv_bfloat16 ha[4], la[4];
    float f[4] = {v.x, v.y, v.z, v.w};
#pragma unroll
    for (int j = 0; j < 4; j++) {
        ha[j] = __float2bfloat16(f[j]);
        la[j] = __float2bfloat16(f[j] - __bfloat162float(ha[j]));
    }
    ((uint2*)h)[i] = *(const uint2*)ha;
    ((uint2*)l)[i] = *(const uint2*)la;
}

// W [K,N] fp32 -> Wt hi/lo [N,K] bf16
__global__ __launch_bounds__(256) void tsplit_kernel(
    const float* __restrict__ W, __nv_bfloat16* __restrict__ Th,
    __nv_bfloat16* __restrict__ Tl)
{
    __shared__ float t[32][33];
    const int n0 = blockIdx.x * 32, k0 = blockIdx.y * 32;
    const int tx = threadIdx.x, ty = threadIdx.y;  // 32 x 8
    for (int i = ty; i < 32; i += 8)
        t[i][tx] = W[(size_t)(k0 + i) * DM + n0 + tx];
    __syncthreads();
    for (int i = ty; i < 32; i += 8) {
        float v = t[tx][i];  // = W[k0+tx][n0+i]
        __nv_bfloat16 hi = __float2bfloat16(v);
        __nv_bfloat16 lo = __float2bfloat16(v - __bfloat162float(hi));
        Th[(size_t)(n0 + i) * DM + k0 + tx] = hi;
        Tl[(size_t)(n0 + i) * DM + k0 + tx] = lo;
    }
}

// ---------------------------------------------------------------------------
// mma.sync GEMM: C[M,N] = A[M,K] @ Wt^T + bias via bf16x3 split.
// SPLIT=true: write (C+bias)*scale as bf16 hi/lo pair arrays (for Q/K/V).
// SPLIT=false: write fp32 C+bias.
// CTA 128x128 tile, 256 threads (8 warps 2x4), warp tile 64x32, BK=64.
// ---------------------------------------------------------------------------
constexpr int GK = 64;
constexpr int GPAD = 72;
constexpr int GT_BYTES = 128 * GPAD * 2;          // 18432 per tile
constexpr int SMG_TOTAL = 4 * GT_BYTES;           // 73728

template<bool SPLIT>
__global__ __launch_bounds__(256) void gemm_mma(
    const __nv_bfloat16* __restrict__ Ah, const __nv_bfloat16* __restrict__ Al,
    const __nv_bfloat16* __restrict__ Wh0, const __nv_bfloat16* __restrict__ Wl0,
    const float* __restrict__ b0, const float* __restrict__ b1,
    const float* __restrict__ b2,
    float* __restrict__ F0,
    __nv_bfloat16* __restrict__ H0, __nv_bfloat16* __restrict__ H1,
    __nv_bfloat16* __restrict__ H2,
    __nv_bfloat16* __restrict__ L0, __nv_bfloat16* __restrict__ L1,
    __nv_bfloat16* __restrict__ L2)
{
    extern __shared__ char smem[];
    const int z = blockIdx.z;
    const __nv_bfloat16* Wh = Wh0 + (size_t)z * DM * DM;
    const __nv_bfloat16* Wl = Wl0 + (size_t)z * DM * DM;
    const float* bias = (z == 0) ? b0 : ((z == 1) ? b1 : b2);

    const int tid  = threadIdx.x;
    const int wid  = tid >> 5, lane = tid & 31;
    const int mBase = blockIdx.y * 128, nBase = blockIdx.x * 128;

    const uint32_t sb = smem_u32(smem);
    const uint32_t sAH = sb;
    const uint32_t sAL = sb + GT_BYTES;
    const uint32_t sBH = sb + 2 * GT_BYTES;
    const uint32_t sBL = sb + 3 * GT_BYTES;

    const int wm = wid >> 2, wn = wid & 3;
    const int mrow0 = wm * 64, nrow0 = wn * 32;

    const uint32_t aOff = (uint32_t)(((lane & 7) + ((lane >> 3) & 1) * 8) * 144
                                     + (lane >> 4) * 16);
    const int l15 = lane & 15;
    const uint32_t bOff = (uint32_t)((l15 & 7) * 144 + (l15 >> 3) * 16);

    const int frow = tid >> 3;
    const int fcol = (tid & 7) * 8;

    const __nv_bfloat16* gAh = Ah + (size_t)mBase * DM;
    const __nv_bfloat16* gAl = Al + (size_t)mBase * DM;
    const __nv_bfloat16* gBh = Wh + (size_t)nBase * DM;
    const __nv_bfloat16* gBl = Wl + (size_t)nBase * DM;

    float c[4][4][4];
#pragma unroll
    for (int i = 0; i < 4; i++)
#pragma unroll
        for (int j = 0; j < 4; j++)
#pragma unroll
            for (int e = 0; e < 4; e++) c[i][j][e] = 0.0f;

    for (int k0 = 0; k0 < DM; k0 += GK) {
        __syncthreads();
#pragma unroll
        for (int p = 0; p < 4; p++) {
            const int row = p * 32 + frow;
            const size_t go = (size_t)row * DM + k0 + fcol;
            const uint32_t so = (uint32_t)(row * GPAD + fcol) * 2;
            *(uint4*)(smem + 0 * GT_BYTES + so) = *(const uint4*)(gAh + go);
            *(uint4*)(smem + 1 * GT_BYTES + so) = *(const uint4*)(gAl + go);
            *(uint4*)(smem + 2 * GT_BYTES + so) = *(const uint4*)(gBh + go);
            *(uint4*)(smem + 3 * GT_BYTES + so) = *(const uint4*)(gBl + go);
        }
        __syncthreads();

#pragma unroll
        for (int ks = 0; ks < GK / 16; ks++) {
            const uint32_t kb = (uint32_t)(ks * 32);
            uint32_t ah[4][4], al[4][4], bh[4][2], bl[4][2];
#pragma unroll
            for (int mf = 0; mf < 4; mf++) {
                const uint32_t ro = (uint32_t)((mrow0 + mf * 16) * 144) + kb + aOff;
                ldmx4(ah[mf], sAH + ro);
                ldmx4(al[mf], sAL + ro);
            }
#pragma unroll
            for (int nf = 0; nf < 4; nf++) {
                const uint32_t ro = (uint32_t)((nrow0 + nf * 8) * 144) + kb + bOff;
                ldmx2(bh[nf], sBH + ro);
                ldmx2(bl[nf], sBL + ro);
            }
#pragma unroll
            for (int mf = 0; mf < 4; mf++)
#pragma unroll
                for (int nf = 0; nf < 4; nf++) {
                    mma16816(c[mf][nf], ah[mf], bh[nf]);
                    mma16816(c[mf][nf], al[mf], bh[nf]);
                    mma16816(c[mf][nf], ah[mf], bl[nf]);
                }
        }
    }

    const int crow = lane >> 2, ccol = (lane & 3) * 2;
    if (SPLIT) {
        __nv_bfloat16* Hd = (z == 0) ? H0 : ((z == 1) ? H1 : H2);
        __nv_bfloat16* Ld = (z == 0) ? L0 : ((z == 1) ? L1 : L2);
        const float scale = (z == 0) ? 0.125f : 1.0f;   // fold 1/sqrt(DK) into Q
#pragma unroll
        for (int mf = 0; mf < 4; mf++) {
#pragma unroll
            for (int nf = 0; nf < 4; nf++) {
                const int r  = mBase + mrow0 + mf * 16 + crow;
                const int cc = nBase + nrow0 + nf * 8 + ccol;
                const float bx = bias[cc], by = bias[cc + 1];
#pragma unroll
                for (int half = 0; half < 2; half++) {
                    const int rr = r + half * 8;
                    float v0 = (c[mf][nf][half * 2 + 0] + bx) * scale;
                    float v1 = (c[mf][nf][half * 2 + 1] + by) * scale;
                    __nv_bfloat16 h0 = __float2bfloat16(v0);
                    __nv_bfloat16 h1 = __float2bfloat16(v1);
                    __nv_bfloat16 r0 = __float2bfloat16(v0 - __bfloat162float(h0));
                    __nv_bfloat16 r1 = __float2bfloat16(v1 - __bfloat162float(h1));
                    *(uint32_t*)(Hd + (size_t)rr * DM + cc) = pack_bf2(h0, h1);
                    *(uint32_t*)(Ld + (size_t)rr * DM + cc) = pack_bf2(r0, r1);
                }
            }
        }
    } else {
#pragma unroll
        for (int mf = 0; mf < 4; mf++) {
#pragma unroll
            for (int nf = 0; nf < 4; nf++) {
                const int r  = mBase + mrow0 + mf * 16 + crow;
                const int cc = nBase + nrow0 + nf * 8 + ccol;
                const float bx = bias[cc], by = bias[cc + 1];
                float2 v0 = { c[mf][nf][0] + bx, c[mf][nf][1] + by };
                float2 v1 = { c[mf][nf][2] + bx, c[mf][nf][3] + by };
                *(float2*)(F0 + (size_t)r * DM + cc)       = v0;
                *(float2*)(F0 + (size_t)(r + 8) * DM + cc) = v1;
            }
        }
    }
}

// ---------------------------------------------------------------------------
// Flash attention on tensor cores (mma.sync, bf16x3 split).
// CTA: 128 q-rows for one (b,h); 8 warps x 16 rows. KV tiles of 64.
// Q hi/lo preloaded to registers; P never round-trips through smem.
// smem: Qh,Ql [128][72]; Kh,Kl [64][72]; Vh,Vl [64][72]  (bf16, pad 72)
// ---------------------------------------------------------------------------
constexpr int AT_Q  = 0;                      // byte offsets in smem
constexpr int AT_QL = 128 * 144;              // 18432
constexpr int AT_KH = 2 * 128 * 144;          // 36864
constexpr int AT_KL = AT_KH + 64 * 144;       // 46080
constexpr int AT_VH = AT_KL + 64 * 144;       // 55296
constexpr int AT_VL = AT_VH + 64 * 144;       // 64512
constexpr int SMA_TOTAL = AT_VL + 64 * 144;   // 73728

__global__ __launch_bounds__(256) void attn_mma(
    const __nv_bfloat16* __restrict__ Qh, const __nv_bfloat16* __restrict__ Ql,
    const __nv_bfloat16* __restrict__ Kh, const __nv_bfloat16* __restrict__ Kl,
    const __nv_bfloat16* __restrict__ Vh, const __nv_bfloat16* __restrict__ Vl,
    __nv_bfloat16* __restrict__ Oh, __nv_bfloat16* __restrict__ Ol)
{
    extern __shared__ char smem[];
    const uint32_t sb = smem_u32(smem);
    const int tid = threadIdx.x;
    const int wid = tid >> 5, lane = tid & 31;
    const int b = blockIdx.z, h = blockIdx.y;
    const int q0 = blockIdx.x * 128;
    const int hc = h * DK;

    // ---- fill Q tile (128 x 64 bf16, hi+lo), rows tid>>1, 32 cols each
    {
        const int row = tid >> 1, cb = (tid & 1) * 32;
        const size_t go = (size_t)(b * S + q0 + row) * DM + hc + cb;
        const uint32_t so = (uint32_t)(row * 144 + cb * 2);
#pragma unroll
        for (int u = 0; u < 4; u++) {
            *(uint4*)(smem + AT_Q  + so + u * 16) = *(const uint4*)(Qh + go + u * 8);
            *(uint4*)(smem + AT_QL + so + u * 16) = *(const uint4*)(Ql + go + u * 8);
        }
    }
    __syncthreads();

    // ---- preload Q fragments (warp rows wid*16 .. +15, 4 k-steps)
    const uint32_t aOff = (uint32_t)(((lane & 7) + ((lane >> 3) & 1) * 8) * 144
                                     + (lane >> 4) * 16);
    const int l15 = lane & 15;
    const uint32_t bOff = (uint32_t)((l15 & 7) * 144 + (l15 >> 3) * 16);
    const uint32_t vOff = (uint32_t)(l15 * 144);

    uint32_t qhF[4][4], qlF[4][4];
#pragma unroll
    for (int kd = 0; kd < 4; kd++) {
        const uint32_t ro = (uint32_t)(wid * 16 * 144) + kd * 32 + aOff;
        ldmx4(qhF[kd], sb + AT_Q  + ro);
        ldmx4(qlF[kd], sb + AT_QL + ro);
    }

    float o[8][4];
#pragma unroll
    for (int nd = 0; nd < 8; nd++)
#pragma unroll
        for (int e = 0; e < 4; e++) o[nd][e] = 0.0f;
    float m0 = -1e30f, m1 = -1e30f, l0 = 0.0f, l1 = 0.0f;

    const int frow = tid >> 2, fcb = (tid & 3) * 16;   // KV fill: 64 rows x 64 cols

    for (int kv0 = 0; kv0 < S; kv0 += 64) {
        // ---- fill K/V tiles
        {
            const size_t go = (size_t)(b * S + kv0 + frow) * DM + hc + fcb;
            const uint32_t so = (uint32_t)(frow * 144 + fcb * 2);
#pragma unroll
            for (int u = 0; u < 2; u++) {
                *(uint4*)(smem + AT_KH + so + u * 16) = *(const uint4*)(Kh + go + u * 8);
                *(uint4*)(smem + AT_KL + so + u * 16) = *(const uint4*)(Kl + go + u * 8);
                *(uint4*)(smem + AT_VH + so + u * 16) = *(const uint4*)(Vh + go + u * 8);
                *(uint4*)(smem + AT_VL + so + u * 16) = *(const uint4*)(Vl + go + u * 8);
            }
        }
        __syncthreads();

        // ---- S = Q K^T  (scores; scale already folded into Q)
        float s[8][4];
#pragma unroll
        for (int nf = 0; nf < 8; nf++)
#pragma unroll
            for (int e = 0; e < 4; e++) s[nf][e] = 0.0f;

#pragma unroll
        for (int nf = 0; nf < 8; nf++) {
#pragma unroll
            for (int kd = 0; kd < 4; kd++) {
                const uint32_t ro = (uint32_t)(nf * 8 * 144) + kd * 32 + bOff;
                uint32_t kh[2], kl[2];
                ldmx2(kh, sb + AT_KH + ro);
                ldmx2(kl, sb + AT_KL + ro);
                mma16816(s[nf], qhF[kd], kh);
                mma16816(s[nf], qlF[kd], kh);
                mma16816(s[nf], qhF[kd], kl);
            }
        }

        // ---- online softmax (rows lane>>2 and +8; 4-lane groups share a row)
        float mx0 = -1e30f, mx1 = -1e30f;
#pragma unroll
        for (int nf = 0; nf < 8; nf++) {
            mx0 = fmaxf(mx0, fmaxf(s[nf][0], s[nf][1]));
            mx1 = fmaxf(mx1, fmaxf(s[nf][2], s[nf][3]));
        }
        mx0 = fmaxf(mx0, __shfl_xor_sync(0xffffffffu, mx0, 1));
        mx0 = fmaxf(mx0, __shfl_xor_sync(0xffffffffu, mx0, 2));
        mx1 = fmaxf(mx1, __shfl_xor_sync(0xffffffffu, mx1, 1));
        mx1 = fmaxf(mx1, __shfl_xor_sync(0xffffffffu, mx1, 2));

        const float nm0 = fmaxf(m0, mx0), nm1 = fmaxf(m1, mx1);
        const float a0 = __expf(m0 - nm0), a1 = __expf(m1 - nm1);
        m0 = nm0; m1 = nm1;

        float ls0 = 0.0f, ls1 = 0.0f;
#pragma unroll
        for (int nf = 0; nf < 8; nf++) {
            s[nf][0] = __expf(s[nf][0] - m0);
            s[nf][1] = __expf(s[nf][1] - m0);
            s[nf][2] = __expf(s[nf][2] - m1);
            s[nf][3] = __expf(s[nf][3] - m1);
            ls0 += s[nf][0] + s[nf][1];
            ls1 += s[nf][2] + s[nf][3];
        }
        ls0 += __shfl_xor_sync(0xffffffffu, ls0, 1);
        ls0 += __shfl_xor_sync(0xffffffffu, ls0, 2);
        ls1 += __shfl_xor_sync(0xffffffffu, ls1, 1);
        ls1 += __shfl_xor_sync(0xffffffffu, ls1, 2);
        l0 = l0 * a0 + ls0;
        l1 = l1 * a1 + ls1;
#pragma unroll
        for (int nd = 0; nd < 8; nd++) {
            o[nd][0] *= a0; o[nd][1] *= a0;
            o[nd][2] *= a1; o[nd][3] *= a1;
        }

        // ---- O += P V  (P frags built in registers from S frags)
#pragma unroll
        for (int kd = 0; kd < 4; kd++) {
            uint32_t pah[4], pal[4];
#pragma unroll
            for (int half = 0; half < 2; half++) {       // half 0: nf=2kd, 1: nf=2kd+1
                const int nf = 2 * kd + half;
#pragma unroll
                for (int rr = 0; rr < 2; rr++) {          // rr 0: rows r0, 1: rows r0+8
                    float p0 = s[nf][rr * 2 + 0];
                    float p1 = s[nf][rr * 2 + 1];
                    __nv_bfloat16 h0 = __float2bfloat16(p0);
                    __nv_bfloat16 h1 = __float2bfloat16(p1);
                    __nv_bfloat16 r0b = __float2bfloat16(p0 - __bfloat162float(h0));
                    __nv_bfloat16 r1b = __float2bfloat16(p1 - __bfloat162float(h1));
                    pah[half * 2 + rr] = pack_bf2(h0, h1);
                    pal[half * 2 + rr] = pack_bf2(r0b, r1b);
                }
            }
#pragma unroll
            for (int nd = 0; nd < 8; nd++) {
                const uint32_t ro = (uint32_t)(kd * 16 * 144) + vOff + nd * 16;
                uint32_t vh[2], vl[2];
                ldmx2t(vh, sb + AT_VH + ro);
                ldmx2t(vl, sb + AT_VL + ro);
                mma16816(o[nd], pah, vh);
                mma16816(o[nd], pal, vh);
                mma16816(o[nd], pah, vl);
            }
        }
        __syncthreads();
    }

    // ---- epilogue: normalize, split to bf16 hi/lo, store
    const float inv0 = 1.0f / l0, inv1 = 1.0f / l1;
    const int gr0 = b * S + q0 + wid * 16 + (lane >> 2);
#pragma unroll
    for (int nd = 0; nd < 8; nd++) {
        const int cc = hc + nd * 8 + (lane & 3) * 2;
#pragma unroll
        for (int half = 0; half < 2; half++) {
            const int rr = gr0 + half * 8;
            const float inv = half ? inv1 : inv0;
            float v0 = o[nd][half * 2 + 0] * inv;
            float v1 = o[nd][half * 2 + 1] * inv;
            __nv_bfloat16 h0 = __float2bfloat16(v0);
            __nv_bfloat16 h1 = __float2bfloat16(v1);
            __nv_bfloat16 r0b = __float2bfloat16(v0 - __bfloat162float(h0));
            __nv_bfloat16 r1b = __float2bfloat16(v1 - __bfloat162float(h1));
            *(uint32_t*)(Oh + (size_t)rr * DM + cc) = pack_bf2(h0, h1);
            *(uint32_t*)(Ol + (size_t)rr * DM + cc) = pack_bf2(r0b, r1b);
        }
    }
}

// ===========================================================================
// Launch
// ===========================================================================
extern "C" void kernel_launch(void* const* d_in, const int* in_sizes, int n_in,
                              void* d_out, int out_size)
{
    const float* x  = (const float*)d_in[0];
    const float* wq = (const float*)d_in[1];
    const float* bq = (const float*)d_in[2];
    const float* wk = (const float*)d_in[3];
    const float* bk = (const float*)d_in[4];
    const float* wv = (const float*)d_in[5];
    const float* bv = (const float*)d_in[6];
    const float* wo = (const float*)d_in[7];
    const float* bo = (const float*)d_in[8];
    float* out = (float*)d_out;

    __nv_bfloat16 *xh, *xl, *qh, *ql, *kh, *kl, *vh, *vl, *ah, *al, *wth, *wtl;
    cudaGetSymbolAddress((void**)&xh, g_xh);
    cudaGetSymbolAddress((void**)&xl, g_xl);
    cudaGetSymbolAddress((void**)&qh, g_qh);
    cudaGetSymbolAddress((void**)&ql, g_ql);
    cudaGetSymbolAddress((void**)&kh, g_kh);
    cudaGetSymbolAddress((void**)&kl, g_kl);
    cudaGetSymbolAddress((void**)&vh, g_vh);
    cudaGetSymbolAddress((void**)&vl, g_vl);
    cudaGetSymbolAddress((void**)&ah, g_ah);
    cudaGetSymbolAddress((void**)&al, g_al);
    cudaGetSymbolAddress((void**)&wth, g_wth);
    cudaGetSymbolAddress((void**)&wtl, g_wtl);

    cudaFuncSetAttribute(gemm_mma<true>,  cudaFuncAttributeMaxDynamicSharedMemorySize, SMG_TOTAL);
    cudaFuncSetAttribute(gemm_mma<false>, cudaFuncAttributeMaxDynamicSharedMemorySize, SMG_TOTAL);
    cudaFuncSetAttribute(attn_mma, cudaFuncAttributeMaxDynamicSharedMemorySize, SMA_TOTAL);

    const size_t WSZ = (size_t)DM * DM;

    // 1) operand prep
    split2_kernel<<<(MR * DM / 4 + 255) / 256, 256>>>(x, xh, xl, MR * DM / 4);
    dim3 gT(DM / 32, DM / 32);
    tsplit_kernel<<<gT, dim3(32, 8)>>>(wq, wth + 0 * WSZ, wtl + 0 * WSZ);
    tsplit_kernel<<<gT, dim3(32, 8)>>>(wk, wth + 1 * WSZ, wtl + 1 * WSZ);
    tsplit_kernel<<<gT, dim3(32, 8)>>>(wv, wth + 2 * WSZ, wtl + 2 * WSZ);
    tsplit_kernel<<<gT, dim3(32, 8)>>>(wo, wth + 3 * WSZ, wtl + 3 * WSZ);

    // 2) fused QKV projections -> bf16 hi/lo (Q pre-scaled by 1/sqrt(DK))
    dim3 gQKV(DM / 128, MR / 128, 3);
    gemm_mma<true><<<gQKV, 256, SMG_TOTAL>>>(
        xh, xl, wth, wtl, bq, bk, bv,
        nullptr, qh, kh, vh, ql, kl, vl);

    // 3) attention (tensor cores) -> bf16 hi/lo
    dim3 gAttn(S / 128, H, B);   // (16, 16, 2)
    attn_mma<<<gAttn, 256, SMA_TOTAL>>>(qh, ql, kh, kl, vh, vl, ah, al);

    // 4) output projection -> fp32 out
    dim3 gO(DM / 128, MR / 128, 1);
    gemm_mma<false><<<gO, 256, SMG_TOTAL>>>(
        ah, al, wth + 3 * WSZ, wtl + 3 * WSZ, bo, bo, bo,
        out, nullptr, nullptr, nullptr, nullptr, nullptr, nullptr);
}

// round 7
// speedup vs baseline: 2.6489x; 1.1003x over previous
#include <cuda_runtime.h>
#include <cuda_bf16.h>
#include <cstdint>
#include <math.h>

// Problem constants
constexpr int B  = 2;
constexpr int S  = 2048;
constexpr int DM = 1024;   // d_model
constexpr int H  = 16;
constexpr int DK = 64;
constexpr int MR = B * S;  // 4096 rows

// ---------------------------------------------------------------------------
// Scratch (allocation-free: __device__ globals)
// ---------------------------------------------------------------------------
__device__ __nv_bfloat16 g_xh[MR * DM];
__device__ __nv_bfloat16 g_xl[MR * DM];
__device__ __nv_bfloat16 g_qh[MR * DM];
__device__ __nv_bfloat16 g_ql[MR * DM];
__device__ __nv_bfloat16 g_kh[MR * DM];
__device__ __nv_bfloat16 g_kl[MR * DM];
__device__ __nv_bfloat16 g_vh[MR * DM];
__device__ __nv_bfloat16 g_vl[MR * DM];
__device__ __nv_bfloat16 g_ah[MR * DM];
__device__ __nv_bfloat16 g_al[MR * DM];
__device__ __nv_bfloat16 g_wth[4 * DM * DM];  // transposed weights, hi part
__device__ __nv_bfloat16 g_wtl[4 * DM * DM];  // transposed weights, lo part

// ---------------------------------------------------------------------------
// mma.sync / ldmatrix / cp.async helpers (non-'a' PTX surface)
// ---------------------------------------------------------------------------
__device__ __forceinline__ uint32_t smem_u32(const void* p) {
    uint32_t a;
    asm("{ .reg .u64 t; cvta.to.shared.u64 t, %1; cvt.u32.u64 %0, t; }"
        : "=r"(a) : "l"(p));
    return a;
}

__device__ __forceinline__ void ldmx4(uint32_t* r, uint32_t addr) {
    asm volatile("ldmatrix.sync.aligned.m8n8.x4.shared.b16 {%0,%1,%2,%3}, [%4];"
                 : "=r"(r[0]), "=r"(r[1]), "=r"(r[2]), "=r"(r[3]) : "r"(addr));
}
__device__ __forceinline__ void ldmx2(uint32_t* r, uint32_t addr) {
    asm volatile("ldmatrix.sync.aligned.m8n8.x2.shared.b16 {%0,%1}, [%2];"
                 : "=r"(r[0]), "=r"(r[1]) : "r"(addr));
}
__device__ __forceinline__ void ldmx2t(uint32_t* r, uint32_t addr) {
    asm volatile("ldmatrix.sync.aligned.m8n8.x2.trans.shared.b16 {%0,%1}, [%2];"
                 : "=r"(r[0]), "=r"(r[1]) : "r"(addr));
}
__device__ __forceinline__ void mma16816(float* c, const uint32_t* a, const uint32_t* b) {
    asm volatile(
        "mma.sync.aligned.m16n8k16.row.col.f32.bf16.bf16.f32 "
        "{%0,%1,%2,%3}, {%4,%5,%6,%7}, {%8,%9}, {%0,%1,%2,%3};"
        : "+f"(c[0]), "+f"(c[1]), "+f"(c[2]), "+f"(c[3])
        : "r"(a[0]), "r"(a[1]), "r"(a[2]), "r"(a[3]), "r"(b[0]), "r"(b[1]));
}
__device__ __forceinline__ void cp16(uint32_t saddr, const void* g) {
    asm volatile("cp.async.cg.shared.global [%0], [%1], 16;"
                 :: "r"(saddr), "l"(g));
}
__device__ __forceinline__ void cp_commit() {
    asm volatile("cp.async.commit_group;");
}
template <int N>
__device__ __forceinline__ void cp_wait() {
    asm volatile("cp.async.wait_group %0;" :: "n"(N));
}

__device__ __forceinline__ uint32_t pack_bf2(__nv_bfloat16 lo, __nv_bfloat16 hi) {
    __nv_bfloat162 t(lo, hi);   // .x = lo 16 bits
    return *(uint32_t*)&t;
}

// ---------------------------------------------------------------------------
// Split / transpose helpers
// ---------------------------------------------------------------------------
__global__ __launch_bounds__(256) void split2_kernel(
    const float* __restrict__ x, __nv_bfloat16* __restrict__ h,
    __nv_bfloat16* __restrict__ l, int n4)
{
    int i = blockIdx.x * blockDim.x + threadIdx.x;
    if (i >= n4) return;
    float4 v = ((const float4*)x)[i];
    __nv_bfloat16 ha[4], la[4];
    float f[4] = {v.x, v.y, v.z, v.w};
#pragma unroll
    for (int j = 0; j < 4; j++) {
        ha[j] = __float2bfloat16(f[j]);
        la[j] = __float2bfloat16(f[j] - __bfloat162float(ha[j]));
    }
    ((uint2*)h)[i] = *(const uint2*)ha;
    ((uint2*)l)[i] = *(const uint2*)la;
}

// W [K,N] fp32 -> Wt hi/lo [N,K] bf16, 4 weights via blockIdx.z
__global__ __launch_bounds__(256) void tsplit_kernel(
    const float* __restrict__ W0, const float* __restrict__ W1,
    const float* __restrict__ W2, const float* __restrict__ W3,
    __nv_bfloat16* __restrict__ Th0, __nv_bfloat16* __restrict__ Tl0)
{
    __shared__ float t[32][33];
    const int z = blockIdx.z;
    const float* W = (z == 0) ? W0 : ((z == 1) ? W1 : ((z == 2) ? W2 : W3));
    __nv_bfloat16* Th = Th0 + (size_t)z * DM * DM;
    __nv_bfloat16* Tl = Tl0 + (size_t)z * DM * DM;
    const int n0 = blockIdx.x * 32, k0 = blockIdx.y * 32;
    const int tx = threadIdx.x, ty = threadIdx.y;  // 32 x 8
    for (int i = ty; i < 32; i += 8)
        t[i][tx] = W[(size_t)(k0 + i) * DM + n0 + tx];
    __syncthreads();
    for (int i = ty; i < 32; i += 8) {
        float v = t[tx][i];  // = W[k0+tx][n0+i]
        __nv_bfloat16 hi = __float2bfloat16(v);
        __nv_bfloat16 lo = __float2bfloat16(v - __bfloat162float(hi));
        Th[(size_t)(n0 + i) * DM + k0 + tx] = hi;
        Tl[(size_t)(n0 + i) * DM + k0 + tx] = lo;
    }
}

// ---------------------------------------------------------------------------
// mma.sync GEMM with 2-stage cp.async pipeline.
// C[M,N] = A[M,K] @ Wt^T + bias via bf16x3 split.
// SPLIT=true: write (C+bias)*scale as bf16 hi/lo. SPLIT=false: fp32 C+bias.
// CTA 128x128 tile, 256 threads (8 warps 2x4), warp tile 64x32, BK=64.
// ---------------------------------------------------------------------------
constexpr int GK = 64;
constexpr int GPAD = 72;
constexpr int GT_BYTES = 128 * GPAD * 2;          // 18432 per tile
constexpr int GSTAGE = 4 * GT_BYTES;              // 73728 per stage
constexpr int SMG_TOTAL = 2 * GSTAGE;             // 147456

template<bool SPLIT>
__global__ __launch_bounds__(256) void gemm_mma(
    const __nv_bfloat16* __restrict__ Ah, const __nv_bfloat16* __restrict__ Al,
    const __nv_bfloat16* __restrict__ Wh0, const __nv_bfloat16* __restrict__ Wl0,
    const float* __restrict__ b0, const float* __restrict__ b1,
    const float* __restrict__ b2,
    float* __restrict__ F0,
    __nv_bfloat16* __restrict__ H0, __nv_bfloat16* __restrict__ H1,
    __nv_bfloat16* __restrict__ H2,
    __nv_bfloat16* __restrict__ L0, __nv_bfloat16* __restrict__ L1,
    __nv_bfloat16* __restrict__ L2)
{
    extern __shared__ char smem[];
    const int z = blockIdx.z;
    const __nv_bfloat16* Wh = Wh0 + (size_t)z * DM * DM;
    const __nv_bfloat16* Wl = Wl0 + (size_t)z * DM * DM;
    const float* bias = (z == 0) ? b0 : ((z == 1) ? b1 : b2);

    const int tid  = threadIdx.x;
    const int wid  = tid >> 5, lane = tid & 31;
    const int mBase = blockIdx.y * 128, nBase = blockIdx.x * 128;

    const uint32_t sb = smem_u32(smem);

    const int wm = wid >> 2, wn = wid & 3;
    const int mrow0 = wm * 64, nrow0 = wn * 32;

    const uint32_t aOff = (uint32_t)(((lane & 7) + ((lane >> 3) & 1) * 8) * 144
                                     + (lane >> 4) * 16);
    const int l15 = lane & 15;
    const uint32_t bOff = (uint32_t)((l15 & 7) * 144 + (l15 >> 3) * 16);

    const int frow = tid >> 3;           // 0..31
    const int fcol = (tid & 7) * 8;      // bf16 elems

    const __nv_bfloat16* gAh = Ah + (size_t)mBase * DM;
    const __nv_bfloat16* gAl = Al + (size_t)mBase * DM;
    const __nv_bfloat16* gBh = Wh + (size_t)nBase * DM;
    const __nv_bfloat16* gBl = Wl + (size_t)nBase * DM;

    // stage fill via cp.async
    auto issue = [&](int it, int st) {
        const int k0 = it * GK;
        const uint32_t s0 = sb + (uint32_t)st * GSTAGE;
#pragma unroll
        for (int p = 0; p < 4; p++) {
            const int row = p * 32 + frow;
            const size_t go = (size_t)row * DM + k0 + fcol;
            const uint32_t so = (uint32_t)(row * GPAD + fcol) * 2;
            cp16(s0 + 0 * GT_BYTES + so, gAh + go);
            cp16(s0 + 1 * GT_BYTES + so, gAl + go);
            cp16(s0 + 2 * GT_BYTES + so, gBh + go);
            cp16(s0 + 3 * GT_BYTES + so, gBl + go);
        }
        cp_commit();
    };

    float c[4][4][4];
#pragma unroll
    for (int i = 0; i < 4; i++)
#pragma unroll
        for (int j = 0; j < 4; j++)
#pragma unroll
            for (int e = 0; e < 4; e++) c[i][j][e] = 0.0f;

    constexpr int NIT = DM / GK;   // 16
    issue(0, 0);

    for (int it = 0; it < NIT; it++) {
        const int cur = it & 1;
        if (it + 1 < NIT) {
            issue(it + 1, cur ^ 1);
            cp_wait<1>();
        } else {
            cp_wait<0>();
        }
        __syncthreads();

        const uint32_t sAH = sb + (uint32_t)cur * GSTAGE;
        const uint32_t sAL = sAH + GT_BYTES;
        const uint32_t sBH = sAH + 2 * GT_BYTES;
        const uint32_t sBL = sAH + 3 * GT_BYTES;

#pragma unroll
        for (int ks = 0; ks < GK / 16; ks++) {
            const uint32_t kb = (uint32_t)(ks * 32);
            uint32_t ah[4][4], al[4][4], bh[4][2], bl[4][2];
#pragma unroll
            for (int mf = 0; mf < 4; mf++) {
                const uint32_t ro = (uint32_t)((mrow0 + mf * 16) * 144) + kb + aOff;
                ldmx4(ah[mf], sAH + ro);
                ldmx4(al[mf], sAL + ro);
            }
#pragma unroll
            for (int nf = 0; nf < 4; nf++) {
                const uint32_t ro = (uint32_t)((nrow0 + nf * 8) * 144) + kb + bOff;
                ldmx2(bh[nf], sBH + ro);
                ldmx2(bl[nf], sBL + ro);
            }
#pragma unroll
            for (int mf = 0; mf < 4; mf++)
#pragma unroll
                for (int nf = 0; nf < 4; nf++) {
                    mma16816(c[mf][nf], ah[mf], bh[nf]);
                    mma16816(c[mf][nf], al[mf], bh[nf]);
                    mma16816(c[mf][nf], ah[mf], bl[nf]);
                }
        }
        __syncthreads();   // stage cur reusable at it+2's issue
    }

    const int crow = lane >> 2, ccol = (lane & 3) * 2;
    if (SPLIT) {
        __nv_bfloat16* Hd = (z == 0) ? H0 : ((z == 1) ? H1 : H2);
        __nv_bfloat16* Ld = (z == 0) ? L0 : ((z == 1) ? L1 : L2);
        const float scale = (z == 0) ? 0.125f : 1.0f;   // fold 1/sqrt(DK) into Q
#pragma unroll
        for (int mf = 0; mf < 4; mf++) {
#pragma unroll
            for (int nf = 0; nf < 4; nf++) {
                const int r  = mBase + mrow0 + mf * 16 + crow;
                const int cc = nBase + nrow0 + nf * 8 + ccol;
                const float bx = bias[cc], by = bias[cc + 1];
#pragma unroll
                for (int half = 0; half < 2; half++) {
                    const int rr = r + half * 8;
                    float v0 = (c[mf][nf][half * 2 + 0] + bx) * scale;
                    float v1 = (c[mf][nf][half * 2 + 1] + by) * scale;
                    __nv_bfloat16 h0 = __float2bfloat16(v0);
                    __nv_bfloat16 h1 = __float2bfloat16(v1);
                    __nv_bfloat16 r0 = __float2bfloat16(v0 - __bfloat162float(h0));
                    __nv_bfloat16 r1 = __float2bfloat16(v1 - __bfloat162float(h1));
                    *(uint32_t*)(Hd + (size_t)rr * DM + cc) = pack_bf2(h0, h1);
                    *(uint32_t*)(Ld + (size_t)rr * DM + cc) = pack_bf2(r0, r1);
                }
            }
        }
    } else {
#pragma unroll
        for (int mf = 0; mf < 4; mf++) {
#pragma unroll
            for (int nf = 0; nf < 4; nf++) {
                const int r  = mBase + mrow0 + mf * 16 + crow;
                const int cc = nBase + nrow0 + nf * 8 + ccol;
                const float bx = bias[cc], by = bias[cc + 1];
                float2 v0 = { c[mf][nf][0] + bx, c[mf][nf][1] + by };
                float2 v1 = { c[mf][nf][2] + bx, c[mf][nf][3] + by };
                *(float2*)(F0 + (size_t)r * DM + cc)       = v0;
                *(float2*)(F0 + (size_t)(r + 8) * DM + cc) = v1;
            }
        }
    }
}

// ---------------------------------------------------------------------------
// Flash attention on tensor cores, 2-stage cp.async K/V pipeline.
// CTA: 128 q-rows for one (b,h); 8 warps x 16 rows. KV tiles of 64.
// smem: Qh,Ql [128][72]; 2 stages of {Kh,Kl,Vh,Vl}[64][72]
// ---------------------------------------------------------------------------
constexpr int AT_Q   = 0;
constexpr int AT_QL  = 128 * 144;                    // 18432
constexpr int AT_KV0 = 2 * 128 * 144;                // 36864
constexpr int KV_T   = 64 * 144;                     // 9216 per tile
constexpr int KV_STAGE = 4 * KV_T;                   // 36864 per stage
constexpr int SMA_TOTAL = AT_KV0 + 2 * KV_STAGE;     // 110592

__global__ __launch_bounds__(256) void attn_mma(
    const __nv_bfloat16* __restrict__ Qh, const __nv_bfloat16* __restrict__ Ql,
    const __nv_bfloat16* __restrict__ Kh, const __nv_bfloat16* __restrict__ Kl,
    const __nv_bfloat16* __restrict__ Vh, const __nv_bfloat16* __restrict__ Vl,
    __nv_bfloat16* __restrict__ Oh, __nv_bfloat16* __restrict__ Ol)
{
    extern __shared__ char smem[];
    const uint32_t sb = smem_u32(smem);
    const int tid = threadIdx.x;
    const int wid = tid >> 5, lane = tid & 31;
    const int b = blockIdx.z, h = blockIdx.y;
    const int q0 = blockIdx.x * 128;
    const int hc = h * DK;

    const int frow = tid >> 2, fcb = (tid & 3) * 16;   // KV fill: 64 rows x 64 cols

    auto issueKV = [&](int kv0, int st) {
        const size_t go = (size_t)(b * S + kv0 + frow) * DM + hc + fcb;
        const uint32_t s0 = sb + AT_KV0 + (uint32_t)st * KV_STAGE;
        const uint32_t so = (uint32_t)(frow * 144 + fcb * 2);
#pragma unroll
        for (int u = 0; u < 2; u++) {
            cp16(s0 + 0 * KV_T + so + u * 16, Kh + go + u * 8);
            cp16(s0 + 1 * KV_T + so + u * 16, Kl + go + u * 8);
            cp16(s0 + 2 * KV_T + so + u * 16, Vh + go + u * 8);
            cp16(s0 + 3 * KV_T + so + u * 16, Vl + go + u * 8);
        }
        cp_commit();
    };

    // ---- fill Q tile (128 x 64 bf16, hi+lo)
    {
        const int row = tid >> 1, cb = (tid & 1) * 32;
        const size_t go = (size_t)(b * S + q0 + row) * DM + hc + cb;
        const uint32_t so = (uint32_t)(row * 144 + cb * 2);
#pragma unroll
        for (int u = 0; u < 4; u++) {
            *(uint4*)(smem + AT_Q  + so + u * 16) = *(const uint4*)(Qh + go + u * 8);
            *(uint4*)(smem + AT_QL + so + u * 16) = *(const uint4*)(Ql + go + u * 8);
        }
    }
    issueKV(0, 0);
    __syncthreads();

    // ---- preload Q fragments
    const uint32_t aOff = (uint32_t)(((lane & 7) + ((lane >> 3) & 1) * 8) * 144
                                     + (lane >> 4) * 16);
    const int l15 = lane & 15;
    const uint32_t bOff = (uint32_t)((l15 & 7) * 144 + (l15 >> 3) * 16);
    const uint32_t vOff = (uint32_t)(l15 * 144);

    uint32_t qhF[4][4], qlF[4][4];
#pragma unroll
    for (int kd = 0; kd < 4; kd++) {
        const uint32_t ro = (uint32_t)(wid * 16 * 144) + kd * 32 + aOff;
        ldmx4(qhF[kd], sb + AT_Q  + ro);
        ldmx4(qlF[kd], sb + AT_QL + ro);
    }

    float o[8][4];
#pragma unroll
    for (int nd = 0; nd < 8; nd++)
#pragma unroll
        for (int e = 0; e < 4; e++) o[nd][e] = 0.0f;
    float m0 = -1e30f, m1 = -1e30f, l0 = 0.0f, l1 = 0.0f;

    constexpr int NT = S / 64;   // 32
    for (int t = 0; t < NT; t++) {
        const int cur = t & 1;
        if (t + 1 < NT) {
            issueKV((t + 1) * 64, cur ^ 1);
            cp_wait<1>();
        } else {
            cp_wait<0>();
        }
        __syncthreads();

        const uint32_t sKH = sb + AT_KV0 + (uint32_t)cur * KV_STAGE;
        const uint32_t sKL = sKH + KV_T;
        const uint32_t sVH = sKH + 2 * KV_T;
        const uint32_t sVL = sKH + 3 * KV_T;

        // ---- S = Q K^T
        float s[8][4];
#pragma unroll
        for (int nf = 0; nf < 8; nf++)
#pragma unroll
            for (int e = 0; e < 4; e++) s[nf][e] = 0.0f;

#pragma unroll
        for (int nf = 0; nf < 8; nf++) {
#pragma unroll
            for (int kd = 0; kd < 4; kd++) {
                const uint32_t ro = (uint32_t)(nf * 8 * 144) + kd * 32 + bOff;
                uint32_t kh[2], kl[2];
                ldmx2(kh, sKH + ro);
                ldmx2(kl, sKL + ro);
                mma16816(s[nf], qhF[kd], kh);
                mma16816(s[nf], qlF[kd], kh);
                mma16816(s[nf], qhF[kd], kl);
            }
        }

        // ---- online softmax
        float mx0 = -1e30f, mx1 = -1e30f;
#pragma unroll
        for (int nf = 0; nf < 8; nf++) {
            mx0 = fmaxf(mx0, fmaxf(s[nf][0], s[nf][1]));
            mx1 = fmaxf(mx1, fmaxf(s[nf][2], s[nf][3]));
        }
        mx0 = fmaxf(mx0, __shfl_xor_sync(0xffffffffu, mx0, 1));
        mx0 = fmaxf(mx0, __shfl_xor_sync(0xffffffffu, mx0, 2));
        mx1 = fmaxf(mx1, __shfl_xor_sync(0xffffffffu, mx1, 1));
        mx1 = fmaxf(mx1, __shfl_xor_sync(0xffffffffu, mx1, 2));

        const float nm0 = fmaxf(m0, mx0), nm1 = fmaxf(m1, mx1);
        const float a0 = __expf(m0 - nm0), a1 = __expf(m1 - nm1);
        m0 = nm0; m1 = nm1;

        float ls0 = 0.0f, ls1 = 0.0f;
#pragma unroll
        for (int nf = 0; nf < 8; nf++) {
            s[nf][0] = __expf(s[nf][0] - m0);
            s[nf][1] = __expf(s[nf][1] - m0);
            s[nf][2] = __expf(s[nf][2] - m1);
            s[nf][3] = __expf(s[nf][3] - m1);
            ls0 += s[nf][0] + s[nf][1];
            ls1 += s[nf][2] + s[nf][3];
        }
        ls0 += __shfl_xor_sync(0xffffffffu, ls0, 1);
        ls0 += __shfl_xor_sync(0xffffffffu, ls0, 2);
        ls1 += __shfl_xor_sync(0xffffffffu, ls1, 1);
        ls1 += __shfl_xor_sync(0xffffffffu, ls1, 2);
        l0 = l0 * a0 + ls0;
        l1 = l1 * a1 + ls1;
#pragma unroll
        for (int nd = 0; nd < 8; nd++) {
            o[nd][0] *= a0; o[nd][1] *= a0;
            o[nd][2] *= a1; o[nd][3] *= a1;
        }

        // ---- O += P V
#pragma unroll
        for (int kd = 0; kd < 4; kd++) {
            uint32_t pah[4], pal[4];
#pragma unroll
            for (int half = 0; half < 2; half++) {
                const int nf = 2 * kd + half;
#pragma unroll
                for (int rr = 0; rr < 2; rr++) {
                    float p0 = s[nf][rr * 2 + 0];
                    float p1 = s[nf][rr * 2 + 1];
                    __nv_bfloat16 h0 = __float2bfloat16(p0);
                    __nv_bfloat16 h1 = __float2bfloat16(p1);
                    __nv_bfloat16 r0b = __float2bfloat16(p0 - __bfloat162float(h0));
                    __nv_bfloat16 r1b = __float2bfloat16(p1 - __bfloat162float(h1));
                    pah[half * 2 + rr] = pack_bf2(h0, h1);
                    pal[half * 2 + rr] = pack_bf2(r0b, r1b);
                }
            }
#pragma unroll
            for (int nd = 0; nd < 8; nd++) {
                const uint32_t ro = (uint32_t)(kd * 16 * 144) + vOff + nd * 16;
                uint32_t vh[2], vl[2];
                ldmx2t(vh, sVH + ro);
                ldmx2t(vl, sVL + ro);
                mma16816(o[nd], pah, vh);
                mma16816(o[nd], pal, vh);
                mma16816(o[nd], pah, vl);
            }
        }
        __syncthreads();
    }

    // ---- epilogue: normalize, split to bf16 hi/lo, store
    const float inv0 = 1.0f / l0, inv1 = 1.0f / l1;
    const int gr0 = b * S + q0 + wid * 16 + (lane >> 2);
#pragma unroll
    for (int nd = 0; nd < 8; nd++) {
        const int cc = hc + nd * 8 + (lane & 3) * 2;
#pragma unroll
        for (int half = 0; half < 2; half++) {
            const int rr = gr0 + half * 8;
            const float inv = half ? inv1 : inv0;
            float v0 = o[nd][half * 2 + 0] * inv;
            float v1 = o[nd][half * 2 + 1] * inv;
            __nv_bfloat16 h0 = __float2bfloat16(v0);
            __nv_bfloat16 h1 = __float2bfloat16(v1);
            __nv_bfloat16 r0b = __float2bfloat16(v0 - __bfloat162float(h0));
            __nv_bfloat16 r1b = __float2bfloat16(v1 - __bfloat162float(h1));
            *(uint32_t*)(Oh + (size_t)rr * DM + cc) = pack_bf2(h0, h1);
            *(uint32_t*)(Ol + (size_t)rr * DM + cc) = pack_bf2(r0b, r1b);
        }
    }
}

// ===========================================================================
// Launch
// ===========================================================================
extern "C" void kernel_launch(void* const* d_in, const int* in_sizes, int n_in,
                              void* d_out, int out_size)
{
    const float* x  = (const float*)d_in[0];
    const float* wq = (const float*)d_in[1];
    const float* bq = (const float*)d_in[2];
    const float* wk = (const float*)d_in[3];
    const float* bk = (const float*)d_in[4];
    const float* wv = (const float*)d_in[5];
    const float* bv = (const float*)d_in[6];
    const float* wo = (const float*)d_in[7];
    const float* bo = (const float*)d_in[8];
    float* out = (float*)d_out;

    __nv_bfloat16 *xh, *xl, *qh, *ql, *kh, *kl, *vh, *vl, *ah, *al, *wth, *wtl;
    cudaGetSymbolAddress((void**)&xh, g_xh);
    cudaGetSymbolAddress((void**)&xl, g_xl);
    cudaGetSymbolAddress((void**)&qh, g_qh);
    cudaGetSymbolAddress((void**)&ql, g_ql);
    cudaGetSymbolAddress((void**)&kh, g_kh);
    cudaGetSymbolAddress((void**)&kl, g_kl);
    cudaGetSymbolAddress((void**)&vh, g_vh);
    cudaGetSymbolAddress((void**)&vl, g_vl);
    cudaGetSymbolAddress((void**)&ah, g_ah);
    cudaGetSymbolAddress((void**)&al, g_al);
    cudaGetSymbolAddress((void**)&wth, g_wth);
    cudaGetSymbolAddress((void**)&wtl, g_wtl);

    cudaFuncSetAttribute(gemm_mma<true>,  cudaFuncAttributeMaxDynamicSharedMemorySize, SMG_TOTAL);
    cudaFuncSetAttribute(gemm_mma<false>, cudaFuncAttributeMaxDynamicSharedMemorySize, SMG_TOTAL);
    cudaFuncSetAttribute(attn_mma, cudaFuncAttributeMaxDynamicSharedMemorySize, SMA_TOTAL);

    const size_t WSZ = (size_t)DM * DM;

    // 1) operand prep
    split2_kernel<<<(MR * DM / 4 + 255) / 256, 256>>>(x, xh, xl, MR * DM / 4);
    dim3 gT(DM / 32, DM / 32, 4);
    tsplit_kernel<<<gT, dim3(32, 8)>>>(wq, wk, wv, wo, wth, wtl);

    // 2) fused QKV projections -> bf16 hi/lo (Q pre-scaled by 1/sqrt(DK))
    dim3 gQKV(DM / 128, MR / 128, 3);
    gemm_mma<true><<<gQKV, 256, SMG_TOTAL>>>(
        xh, xl, wth, wtl, bq, bk, bv,
        nullptr, qh, kh, vh, ql, kl, vl);

    // 3) attention (tensor cores) -> bf16 hi/lo
    dim3 gAttn(S / 128, H, B);   // (16, 16, 2)
    attn_mma<<<gAttn, 256, SMA_TOTAL>>>(qh, ql, kh, kl, vh, vl, ah, al);

    // 4) output projection -> fp32 out
    dim3 gO(DM / 128, MR / 128, 1);
    gemm_mma<false><<<gO, 256, SMG_TOTAL>>>(
        ah, al, wth + 3 * WSZ, wtl + 3 * WSZ, bo, bo, bo,
        out, nullptr, nullptr, nullptr, nullptr, nullptr, nullptr);
}